// round 8
// baseline (speedup 1.0000x reference)
#include <cuda_runtime.h>
#include <cuda_fp16.h>
#include <cstdint>

// Problem constants
#define BATCH 8
#define MDIM 2048
#define MAUG 2049
#define STRIDE 2052        // fp32 Z row stride
#define HSTRIDE 2056       // fp16 Zh row stride (4112 B, 16B aligned)
#define VS 2052            // u/v stride (float4 aligned)
#define CDIM 256
#define NITERS 20
#define RC 64              // rows per col-pass chunk
#define NCHUNK 33          // ceil(2049/64)

#define L2E 1.4426950408889634f
#define LN2 0.6931471805599453f
#define LOGMU_MAIN (-8.317766166719343f)   // norm = -log(4096)
#define LOGMU_TAIL (-0.6931471805599453f)  // -log 2
#define MINUS_NORM (8.317766166719343f)

// Scratch (device globals — no cudaMalloc allowed)
__device__ float  g_Z [(size_t)BATCH * MAUG * STRIDE];   // fp32 master (epilogue)
__device__ __half g_Zh[(size_t)BATCH * MAUG * HSTRIDE];  // fp16, PRE-SCALED by log2e
__device__ float  g_u [BATCH * VS];
__device__ float  g_v [BATCH * VS];
__device__ float  g_pm[(size_t)NCHUNK * BATCH * 2048];   // col-pass partial max (log2 dom.)
__device__ float  g_ps[(size_t)NCHUNK * BATCH * 2048];   // col-pass partial sum

// ---------------- packed f32x2 helpers ----------------
__device__ __forceinline__ unsigned long long pk2(float lo, float hi) {
    unsigned long long r;
    asm("mov.b64 %0, {%1, %2};" : "=l"(r) : "f"(lo), "f"(hi));
    return r;
}
__device__ __forceinline__ void fma2(unsigned long long& acc, unsigned long long a, unsigned long long b) {
    asm("fma.rn.f32x2 %0, %1, %2, %0;" : "+l"(acc) : "l"(a), "l"(b));
}
__device__ __forceinline__ float2 unpk(unsigned long long p) {
    float2 f;
    asm("mov.b64 {%0, %1}, %2;" : "=f"(f.x), "=f"(f.y) : "l"(p));
    return f;
}

// ---------------- GEMM: scores[b] = A[b] @ B[b]^T (fp32 Z + log2e-scaled fp16 Zh) ----------------
__global__ __launch_bounds__(256, 2) void gemm_kernel(const float* __restrict__ A,
                                                      const float* __restrict__ Bm) {
    const int b = blockIdx.z;
    const float* Ab = A  + (size_t)b * MDIM * CDIM;
    const float* Bb = Bm + (size_t)b * MDIM * CDIM;
    float* Cb = g_Z + (size_t)b * MAUG * STRIDE;
    __half* Hb = g_Zh + (size_t)b * MAUG * HSTRIDE;
    const int bm = blockIdx.y * 128, bn = blockIdx.x * 128;

    __shared__ float As[16][132];
    __shared__ float Bs[16][132];

    const int tid = threadIdx.x;
    const int tx = tid & 15, ty = tid >> 4;

    unsigned long long acc[8][4];
#pragma unroll
    for (int i = 0; i < 8; i++)
#pragma unroll
        for (int j = 0; j < 4; j++) acc[i][j] = 0ull;

    for (int k0 = 0; k0 < CDIM; k0 += 16) {
#pragma unroll
        for (int l = 0; l < 2; l++) {
            int idx = tid + l * 256;
            int r = idx >> 2, q = idx & 3;
            float4 va = *(const float4*)(Ab + (size_t)(bm + r) * CDIM + k0 + q * 4);
            As[q * 4 + 0][r] = va.x; As[q * 4 + 1][r] = va.y;
            As[q * 4 + 2][r] = va.z; As[q * 4 + 3][r] = va.w;
            float4 vb = *(const float4*)(Bb + (size_t)(bn + r) * CDIM + k0 + q * 4);
            Bs[q * 4 + 0][r] = vb.x; Bs[q * 4 + 1][r] = vb.y;
            Bs[q * 4 + 2][r] = vb.z; Bs[q * 4 + 3][r] = vb.w;
        }
        __syncthreads();
#pragma unroll
        for (int k = 0; k < 16; k++) {
            float4 a0 = *(const float4*)&As[k][ty * 8];
            float4 a1 = *(const float4*)&As[k][ty * 8 + 4];
            float4 b0 = *(const float4*)&Bs[k][tx * 8];
            float4 b1 = *(const float4*)&Bs[k][tx * 8 + 4];
            unsigned long long pb[4] = { pk2(b0.x, b0.y), pk2(b0.z, b0.w),
                                         pk2(b1.x, b1.y), pk2(b1.z, b1.w) };
            float av[8] = { a0.x, a0.y, a0.z, a0.w, a1.x, a1.y, a1.z, a1.w };
#pragma unroll
            for (int i = 0; i < 8; i++) {
                unsigned long long pa = pk2(av[i], av[i]);
#pragma unroll
                for (int j = 0; j < 4; j++) fma2(acc[i][j], pa, pb[j]);
            }
        }
        __syncthreads();
    }
#pragma unroll
    for (int i = 0; i < 8; i++) {
        const int row = bm + ty * 8 + i;
        float* cp = Cb + (size_t)row * STRIDE + bn + tx * 8;
        __half2* hp = (__half2*)(Hb + (size_t)row * HSTRIDE + bn + tx * 8);
#pragma unroll
        for (int j = 0; j < 4; j++) {
            float2 f = unpk(acc[i][j]);
            *(float2*)(cp + 2 * j) = f;
            hp[j] = __floats2half2_rn(f.x * L2E, f.y * L2E);
        }
    }
}

// ---------------- fill dustbins, init v ----------------
__global__ void fill_kernel(const float* __restrict__ binp) {
    const int b = blockIdx.y;
    const int t = blockIdx.x * blockDim.x + threadIdx.x;
    if (t >= MAUG) return;
    const float bin = binp[0];
    const __half hb = __float2half_rn(bin * L2E);
    float*  Zb = g_Z  + (size_t)b * MAUG * STRIDE;
    __half* Hb = g_Zh + (size_t)b * MAUG * HSTRIDE;
    Zb[(size_t)MDIM * STRIDE + t] = bin;
    Hb[(size_t)MDIM * HSTRIDE + t] = hb;
    if (t < MDIM) {
        Zb[(size_t)t * STRIDE + MDIM] = bin;
        Hb[(size_t)t * HSTRIDE + MDIM] = hb;
    }
    g_v[b * VS + t] = 0.0f;
}

// ---------------- row pass: u[i] = logmu(i) - lse_j(Z[i,j]+v[j]) ----------------
// warp per row; two-pass over 32 half2 registers; fp16x2 exp2.
__global__ __launch_bounds__(256) void sinkhorn_row(const float* __restrict__ binp) {
    const int b = blockIdx.y;
    __shared__ __align__(16) __half2 w2[1024];   // (v[j]-vbar)*L2E, cols 0..2047
    __shared__ float swdust;
    const int tid = threadIdx.x;
    const float vbar = g_v[b * VS];
    {
        const float4* v4 = (const float4*)(g_v + b * VS);
        for (int t = tid; t < 512; t += 256) {
            float4 vv = v4[t];
            w2[2 * t]     = __floats2half2_rn((vv.x - vbar) * L2E, (vv.y - vbar) * L2E);
            w2[2 * t + 1] = __floats2half2_rn((vv.z - vbar) * L2E, (vv.w - vbar) * L2E);
        }
        if (tid == 0) swdust = (g_v[b * VS + MDIM] - vbar) * L2E;
    }
    __syncthreads();

    const int wid = tid >> 5, lane = tid & 31;
    const int i = blockIdx.x * 8 + wid;
    if (i >= MAUG) return;

    const uint4* zp = (const uint4*)(g_Zh + ((size_t)b * MAUG + i) * HSTRIDE);
    const uint4* wp = (const uint4*)w2;

    __half2 x[8][4];
    __half2 m2 = __half2half2(__ushort_as_half(0xFC00u));   // -inf
#pragma unroll
    for (int k = 0; k < 8; k++) {
        uint4 q = zp[lane + 32 * k];
        uint4 w = wp[lane + 32 * k];
        x[k][0] = __hadd2(*(__half2*)&q.x, *(__half2*)&w.x);
        x[k][1] = __hadd2(*(__half2*)&q.y, *(__half2*)&w.y);
        x[k][2] = __hadd2(*(__half2*)&q.z, *(__half2*)&w.z);
        x[k][3] = __hadd2(*(__half2*)&q.w, *(__half2*)&w.w);
        m2 = __hmax2(m2, __hmax2(__hmax2(x[k][0], x[k][1]), __hmax2(x[k][2], x[k][3])));
    }
    float Mf = fmaxf(__low2float(m2), __high2float(m2));
#pragma unroll
    for (int o = 16; o > 0; o >>= 1) Mf = fmaxf(Mf, __shfl_xor_sync(0xffffffffu, Mf, o));
    const __half2 mh = __float2half2_rn(Mf);   // exact (value came from a half)

    float s0 = 0.0f, s1 = 0.0f;
#pragma unroll
    for (int k = 0; k < 8; k++) {
        __half2 e0 = h2exp2(__hsub2(x[k][0], mh));
        __half2 e1 = h2exp2(__hsub2(x[k][1], mh));
        __half2 e2 = h2exp2(__hsub2(x[k][2], mh));
        __half2 e3 = h2exp2(__hsub2(x[k][3], mh));
        __half2 e = __hadd2(__hadd2(e0, e1), __hadd2(e2, e3));
        float2 f = __half22float2(e);
        s0 += f.x; s1 += f.y;
    }
    if (lane == 0) s0 += exp2f(binp[0] * L2E + swdust - Mf);   // dustbin column term
    float s = s0 + s1;
#pragma unroll
    for (int o = 16; o > 0; o >>= 1) s += __shfl_xor_sync(0xffffffffu, s, o);
    if (lane == 0) {
        float lse = LN2 * (Mf + log2f(s)) + vbar;
        g_u[b * VS + i] = ((i == MDIM) ? LOGMU_TAIL : LOGMU_MAIN) - lse;
    }
}

// ---------------- col pass: partial per-column (m, s) over a 64-row chunk ----------------
// thread owns 8 consecutive cols; reads Zh row-major (coalesced). cols 0..2047.
__global__ __launch_bounds__(256) void sinkhorn_col() {
    const int b = blockIdx.y, chunk = blockIdx.x;
    const int c0 = threadIdx.x * 8;
    const float ubar = g_u[b * VS];

    __half2 m2[4];
    float s[8];
#pragma unroll
    for (int k = 0; k < 4; k++) m2[k] = __half2half2(__ushort_as_half(0xFC00u));
#pragma unroll
    for (int k = 0; k < 8; k++) s[k] = 0.0f;

    const int r0 = chunk * RC;
    const int rend = (r0 + RC < MAUG) ? (r0 + RC) : MAUG;
    const __half* zbase = g_Zh + (size_t)b * MAUG * HSTRIDE + c0;

#pragma unroll 4
    for (int r = r0; r < rend; r++) {
        float uf = g_u[b * VS + r];                       // broadcast, L1 hit
        __half2 u2 = __float2half2_rn((uf - ubar) * L2E);
        uint4 q = *(const uint4*)(zbase + (size_t)r * HSTRIDE);
        __half2 xx[4];
        xx[0] = __hadd2(*(__half2*)&q.x, u2);
        xx[1] = __hadd2(*(__half2*)&q.y, u2);
        xx[2] = __hadd2(*(__half2*)&q.z, u2);
        xx[3] = __hadd2(*(__half2*)&q.w, u2);
        __half2 nm[4];
        unsigned ch = 0;
#pragma unroll
        for (int k = 0; k < 4; k++) {
            nm[k] = __hmax2(m2[k], xx[k]);
            ch |= (*(unsigned*)&nm[k]) ^ (*(unsigned*)&m2[k]);
        }
        if (ch) {   // a column saw a new max: rescale its fp32 sum (rare after warmup)
#pragma unroll
            for (int k = 0; k < 4; k++) {
                float2 om = __half22float2(m2[k]);
                float2 nf = __half22float2(nm[k]);
                s[2 * k]     *= exp2f(fminf(om.x - nf.x, 0.0f));   // fminf kills (-inf)-(-inf) NaN
                s[2 * k + 1] *= exp2f(fminf(om.y - nf.y, 0.0f));
            }
        }
#pragma unroll
        for (int k = 0; k < 4; k++) {
            m2[k] = nm[k];
            __half2 e = h2exp2(__hsub2(xx[k], m2[k]));
            float2 f = __half22float2(e);
            s[2 * k] += f.x; s[2 * k + 1] += f.y;
        }
    }
    float* pm = g_pm + (size_t)(chunk * BATCH + b) * 2048 + c0;
    float* ps = g_ps + (size_t)(chunk * BATCH + b) * 2048 + c0;
#pragma unroll
    for (int k = 0; k < 4; k++) {
        float2 mf = __half22float2(m2[k]);
        pm[2 * k] = mf.x; pm[2 * k + 1] = mf.y;
        ps[2 * k] = s[2 * k]; ps[2 * k + 1] = s[2 * k + 1];
    }
}

// ---------------- col finish: merge chunk partials -> v; block 8 computes v[2048] ----------------
__global__ __launch_bounds__(256) void sinkhorn_colfin(const float* __restrict__ binp) {
    const int b = blockIdx.y;
    if (blockIdx.x == 8) {
        // v[2048] = LOGMU_TAIL - (bin + lse_i(u[i]))
        const int tid = threadIdx.x;
        float m = -3.0e38f, s = 0.0f;
        for (int i = tid; i < MAUG; i += 256) {
            float u = g_u[b * VS + i];
            if (u > m) { s *= __expf(m - u); m = u; }
            s += __expf(u - m);
        }
        __shared__ float sm[8], ss[8];
#pragma unroll
        for (int o = 16; o > 0; o >>= 1) {
            float mo = __shfl_xor_sync(0xffffffffu, m, o);
            float so = __shfl_xor_sync(0xffffffffu, s, o);
            float nm = fmaxf(m, mo);
            s = s * __expf(m - nm) + so * __expf(mo - nm);
            m = nm;
        }
        if ((tid & 31) == 0) { sm[tid >> 5] = m; ss[tid >> 5] = s; }
        __syncthreads();
        if (tid == 0) {
            float M = sm[0], S = ss[0];
#pragma unroll
            for (int w = 1; w < 8; w++) {
                float nm = fmaxf(M, sm[w]);
                S = S * __expf(M - nm) + ss[w] * __expf(sm[w] - nm);
                M = nm;
            }
            g_v[b * VS + MDIM] = LOGMU_TAIL - (binp[0] + M + logf(S));
        }
        return;
    }
    const int c = blockIdx.x * 256 + threadIdx.x;
    const float ubar = g_u[b * VS];
    float M = -3.0e38f, S = 0.0f;
#pragma unroll
    for (int ch = 0; ch < NCHUNK; ch++) {
        float m = g_pm[(size_t)(ch * BATCH + b) * 2048 + c];
        float s = g_ps[(size_t)(ch * BATCH + b) * 2048 + c];
        float nm = fmaxf(M, m);
        S = S * exp2f(fminf(M - nm, 0.0f)) + s * exp2f(fminf(m - nm, 0.0f));
        M = nm;
    }
    float lse = LN2 * (M + log2f(S)) + ubar;
    g_v[b * VS + c] = LOGMU_MAIN - lse;
}

// ---------------- epilogue: out = Z(fp32) + u + v - norm ----------------
__global__ void final_kernel(float* __restrict__ out) {
    const int b = blockIdx.z, i = blockIdx.y;
    const int j = blockIdx.x * 256 + threadIdx.x;
    if (j >= MAUG) return;
    float z = g_Z[((size_t)b * MAUG + i) * STRIDE + j];
    float u = g_u[b * VS + i];
    float v = g_v[b * VS + j];
    out[((size_t)b * MAUG + i) * MAUG + j] = z + u + v + MINUS_NORM;
}

// ---------------- launch ----------------
extern "C" void kernel_launch(void* const* d_in, const int* in_sizes, int n_in,
                              void* d_out, int out_size) {
    const float* f0  = (const float*)d_in[0];  // feat_c0 [8,2048,256]
    const float* f1  = (const float*)d_in[1];  // feat_c1 [8,2048,256]
    const float* bin = (const float*)d_in[2];  // bin_score scalar
    float* out = (float*)d_out;                // [8,2049,2049] fp32

    gemm_kernel<<<dim3(16, 16, BATCH), 256>>>(f0, f1);
    fill_kernel<<<dim3((MAUG + 255) / 256, BATCH), 256>>>(bin);
    for (int it = 0; it < NITERS; ++it) {
        sinkhorn_row<<<dim3(257, BATCH), 256>>>(bin);      // update u
        sinkhorn_col<<<dim3(NCHUNK, BATCH), 256>>>();      // col partials
        sinkhorn_colfin<<<dim3(9, BATCH), 256>>>(bin);     // merge -> v
    }
    final_kernel<<<dim3((MAUG + 255) / 256, MAUG, BATCH), 256>>>(out);
}

// round 11
// speedup vs baseline: 1.1262x; 1.1262x over previous
#include <cuda_runtime.h>
#include <cuda_fp16.h>
#include <cstdint>

// Problem constants
#define BATCH 8
#define MDIM 2048
#define MAUG 2049
#define STRIDE 2052        // fp32 Z row stride
#define HSTRIDE 2056       // fp16 row stride (4112 B, 16B aligned)
#define VS 2052            // u/v stride
#define CDIM 256
#define NITERS 20

#define L2E 1.4426950408889634f
#define LN2 0.6931471805599453f
#define LOGMU_MAIN (-8.317766166719343f)   // norm = -log(4096)
#define LOGMU_TAIL (-0.6931471805599453f)  // -log 2
#define MINUS_NORM (8.317766166719343f)

// Scratch (device globals — no cudaMalloc allowed)
__device__ float  g_Z  [(size_t)BATCH * MAUG * STRIDE];   // fp32 master (epilogue)
__device__ __half g_Zh [(size_t)BATCH * MAUG * HSTRIDE];  // fp16, PRE-SCALED by log2e
__device__ __half g_ZTh[(size_t)BATCH * MAUG * HSTRIDE];  // transpose (constant, built once)
__device__ float  g_u  [BATCH * VS];
__device__ float  g_v  [BATCH * VS];

// ---------------- fast math helpers ----------------
__device__ __forceinline__ float ex2f(float x) { float r; asm("ex2.approx.ftz.f32 %0,%1;" : "=f"(r) : "f"(x)); return r; }
__device__ __forceinline__ float lg2f(float x) { float r; asm("lg2.approx.f32 %0,%1;" : "=f"(r) : "f"(x)); return r; }

// ---------------- packed f32x2 helpers ----------------
__device__ __forceinline__ unsigned long long pk2(float lo, float hi) {
    unsigned long long r;
    asm("mov.b64 %0, {%1, %2};" : "=l"(r) : "f"(lo), "f"(hi));
    return r;
}
__device__ __forceinline__ void fma2(unsigned long long& acc, unsigned long long a, unsigned long long b) {
    asm("fma.rn.f32x2 %0, %1, %2, %0;" : "+l"(acc) : "l"(a), "l"(b));
}
__device__ __forceinline__ float2 unpk(unsigned long long p) {
    float2 f;
    asm("mov.b64 {%0, %1}, %2;" : "=f"(f.x), "=f"(f.y) : "l"(p));
    return f;
}

// ---------------- GEMM: scores[b] = A[b] @ B[b]^T (fp32 Z + log2e-scaled fp16 Zh) ----------------
__global__ __launch_bounds__(256, 2) void gemm_kernel(const float* __restrict__ A,
                                                      const float* __restrict__ Bm) {
    const int b = blockIdx.z;
    const float* Ab = A  + (size_t)b * MDIM * CDIM;
    const float* Bb = Bm + (size_t)b * MDIM * CDIM;
    float* Cb = g_Z + (size_t)b * MAUG * STRIDE;
    __half* Hb = g_Zh + (size_t)b * MAUG * HSTRIDE;
    const int bm = blockIdx.y * 128, bn = blockIdx.x * 128;

    __shared__ float As[16][132];
    __shared__ float Bs[16][132];

    const int tid = threadIdx.x;
    const int tx = tid & 15, ty = tid >> 4;

    unsigned long long acc[8][4];
#pragma unroll
    for (int i = 0; i < 8; i++)
#pragma unroll
        for (int j = 0; j < 4; j++) acc[i][j] = 0ull;

    for (int k0 = 0; k0 < CDIM; k0 += 16) {
#pragma unroll
        for (int l = 0; l < 2; l++) {
            int idx = tid + l * 256;
            int r = idx >> 2, q = idx & 3;
            float4 va = *(const float4*)(Ab + (size_t)(bm + r) * CDIM + k0 + q * 4);
            As[q * 4 + 0][r] = va.x; As[q * 4 + 1][r] = va.y;
            As[q * 4 + 2][r] = va.z; As[q * 4 + 3][r] = va.w;
            float4 vb = *(const float4*)(Bb + (size_t)(bn + r) * CDIM + k0 + q * 4);
            Bs[q * 4 + 0][r] = vb.x; Bs[q * 4 + 1][r] = vb.y;
            Bs[q * 4 + 2][r] = vb.z; Bs[q * 4 + 3][r] = vb.w;
        }
        __syncthreads();
#pragma unroll
        for (int k = 0; k < 16; k++) {
            float4 a0 = *(const float4*)&As[k][ty * 8];
            float4 a1 = *(const float4*)&As[k][ty * 8 + 4];
            float4 b0 = *(const float4*)&Bs[k][tx * 8];
            float4 b1 = *(const float4*)&Bs[k][tx * 8 + 4];
            unsigned long long pb[4] = { pk2(b0.x, b0.y), pk2(b0.z, b0.w),
                                         pk2(b1.x, b1.y), pk2(b1.z, b1.w) };
            float av[8] = { a0.x, a0.y, a0.z, a0.w, a1.x, a1.y, a1.z, a1.w };
#pragma unroll
            for (int i = 0; i < 8; i++) {
                unsigned long long pa = pk2(av[i], av[i]);
#pragma unroll
                for (int j = 0; j < 4; j++) fma2(acc[i][j], pa, pb[j]);
            }
        }
        __syncthreads();
    }
#pragma unroll
    for (int i = 0; i < 8; i++) {
        const int row = bm + ty * 8 + i;
        float* cp = Cb + (size_t)row * STRIDE + bn + tx * 8;
        __half2* hp = (__half2*)(Hb + (size_t)row * HSTRIDE + bn + tx * 8);
#pragma unroll
        for (int j = 0; j < 4; j++) {
            float2 f = unpk(acc[i][j]);
            *(float2*)(cp + 2 * j) = f;
            hp[j] = __floats2half2_rn(f.x * L2E, f.y * L2E);
        }
    }
}

// ---------------- fill dustbins (fp32 Z + fp16 Zh), init v ----------------
__global__ void fill_kernel(const float* __restrict__ binp) {
    const int b = blockIdx.y;
    const int t = blockIdx.x * blockDim.x + threadIdx.x;
    if (t >= MAUG) return;
    const float bin = binp[0];
    const __half hb = __float2half_rn(bin * L2E);
    float*  Zb = g_Z  + (size_t)b * MAUG * STRIDE;
    __half* Hb = g_Zh + (size_t)b * MAUG * HSTRIDE;
    Zb[(size_t)MDIM * STRIDE + t] = bin;          // dustbin row (incl. corner)
    Hb[(size_t)MDIM * HSTRIDE + t] = hb;
    if (t < MDIM) {
        Zb[(size_t)t * STRIDE + MDIM] = bin;      // dustbin col
        Hb[(size_t)t * HSTRIDE + MDIM] = hb;
    }
    g_v[b * VS + t] = 0.0f;
}

// ---------------- fp16 transpose Zh -> ZTh (once; Z is constant) ----------------
__global__ __launch_bounds__(256) void transpose_kernel() {
    __shared__ __half ts[64][66];
    const int b = blockIdx.z;
    const __half* Zhb = g_Zh  + (size_t)b * MAUG * HSTRIDE;
    __half* ZTb       = g_ZTh + (size_t)b * MAUG * HSTRIDE;
    const int x0 = blockIdx.x * 64, y0 = blockIdx.y * 64;
    const int tx = threadIdx.x, ty = threadIdx.y;

#pragma unroll
    for (int p = 0; p < 8; p++) {
        const int r = p * 8 + ty;
        const int y = y0 + r, x = x0 + 2 * tx;
        __half2 h = __half2half2(__ushort_as_half(0));
        if (y < MAUG && x + 2 <= HSTRIDE)
            h = *(const __half2*)(Zhb + (size_t)y * HSTRIDE + x);
        *(__half2*)&ts[r][2 * tx] = h;
    }
    __syncthreads();
#pragma unroll
    for (int p = 0; p < 8; p++) {
        const int r = p * 8 + ty;
        const int xo = x0 + r, yc = y0 + 2 * tx;
        if (xo < MAUG && yc + 2 <= HSTRIDE) {
            __half2 h = __halves2half2(ts[2 * tx][r], ts[2 * tx + 1][r]);
            *(__half2*)(ZTb + (size_t)xo * HSTRIDE + yc) = h;
        }
    }
}

// ---------------- Sinkhorn half-pass: 2 warps per row, fp32 math, fp16 stream ----------------
// dir=0: u[i] = logmu(i) - lse_j( Zh[i,j] + v[j] )   over j=0..2048
// dir=1: v[j] = logmu(j) - lse_i( ZTh[j,i] + u[i] )  over i=0..2048
__global__ __launch_bounds__(256) void sinkhorn_half(int dir) {
    const int b = blockIdx.y;
    const __half* Zp = dir ? g_ZTh : g_Zh;
    const float* vin = dir ? g_u : g_v;
    float* uout      = dir ? g_v : g_u;

    __shared__ __align__(16) float wv[2048];   // vin[j] * log2e, cols 0..2047
    __shared__ float sM[8], sS[8];
    const int tid = threadIdx.x;
    {
        const float4* v4 = (const float4*)(vin + b * VS);
        float4* w4 = (float4*)wv;
        for (int t = tid; t < 512; t += 256) {
            float4 vv = v4[t];
            w4[t] = make_float4(vv.x * L2E, vv.y * L2E, vv.z * L2E, vv.w * L2E);
        }
    }
    __syncthreads();

    const int wid = tid >> 5, lane = tid & 31;
    const int row = blockIdx.x * 4 + (wid >> 1);
    const int half = wid & 1;                    // which 1024-col half this warp owns
    const bool valid = row < MAUG;

    float x[32];
    float M = -3.0e38f;
    if (valid) {
        const uint4* zp = (const uint4*)(Zp + ((size_t)b * MAUG + row) * HSTRIDE + half * 1024);
        const float4* w4 = (const float4*)(wv + half * 1024);
#pragma unroll
        for (int r = 0; r < 4; r++) {
            uint4 q = zp[lane + 32 * r];
            float4 wa = w4[(lane + 32 * r) * 2];
            float4 wb = w4[(lane + 32 * r) * 2 + 1];
            float2 f0 = __half22float2(*(__half2*)&q.x);
            float2 f1 = __half22float2(*(__half2*)&q.y);
            float2 f2 = __half22float2(*(__half2*)&q.z);
            float2 f3 = __half22float2(*(__half2*)&q.w);
            x[8 * r + 0] = f0.x + wa.x; x[8 * r + 1] = f0.y + wa.y;
            x[8 * r + 2] = f1.x + wa.z; x[8 * r + 3] = f1.y + wa.w;
            x[8 * r + 4] = f2.x + wb.x; x[8 * r + 5] = f2.y + wb.y;
            x[8 * r + 6] = f3.x + wb.z; x[8 * r + 7] = f3.y + wb.w;
#pragma unroll
            for (int k = 0; k < 8; k++) M = fmaxf(M, x[8 * r + k]);
        }
    }
#pragma unroll
    for (int o = 16; o > 0; o >>= 1) M = fmaxf(M, __shfl_xor_sync(0xffffffffu, M, o));
    sM[wid] = M;
    __syncthreads();
    M = fmaxf(sM[wid], sM[wid ^ 1]);            // full-row max

    float s0 = 0.0f, s1 = 0.0f;
    if (valid) {
#pragma unroll
        for (int k = 0; k < 32; k += 2) {
            s0 += ex2f(x[k] - M);
            s1 += ex2f(x[k + 1] - M);
        }
    }
    float s = s0 + s1;
#pragma unroll
    for (int o = 16; o > 0; o >>= 1) s += __shfl_xor_sync(0xffffffffu, s, o);
    if (lane == 0) sS[wid] = s;
    __syncthreads();
    if (valid && half == 0 && lane == 0) {
        float S = sS[wid] + sS[wid | 1];
        // dustbin element (index 2048 of this row)
        float zd = __half2float(Zp[((size_t)b * MAUG + row) * HSTRIDE + MDIM]);
        float wd = vin[b * VS + MDIM] * L2E;
        S += ex2f(zd + wd - M);
        float lse = LN2 * (M + lg2f(S));
        uout[b * VS + row] = ((row == MDIM) ? LOGMU_TAIL : LOGMU_MAIN) - lse;
    }
}

// ---------------- epilogue: out = Z(fp32) + u + v - norm ----------------
__global__ void final_kernel(float* __restrict__ out) {
    const int b = blockIdx.z, i = blockIdx.y;
    const int j = blockIdx.x * 256 + threadIdx.x;
    if (j >= MAUG) return;
    float z = g_Z[((size_t)b * MAUG + i) * STRIDE + j];
    float u = g_u[b * VS + i];
    float v = g_v[b * VS + j];
    out[((size_t)b * MAUG + i) * MAUG + j] = z + u + v + MINUS_NORM;
}

// ---------------- launch ----------------
extern "C" void kernel_launch(void* const* d_in, const int* in_sizes, int n_in,
                              void* d_out, int out_size) {
    const float* f0  = (const float*)d_in[0];  // feat_c0 [8,2048,256]
    const float* f1  = (const float*)d_in[1];  // feat_c1 [8,2048,256]
    const float* bin = (const float*)d_in[2];  // bin_score scalar
    float* out = (float*)d_out;                // [8,2049,2049] fp32

    gemm_kernel<<<dim3(16, 16, BATCH), 256>>>(f0, f1);
    fill_kernel<<<dim3((MAUG + 255) / 256, BATCH), 256>>>(bin);
    transpose_kernel<<<dim3(33, 33, BATCH), dim3(32, 8)>>>();
    for (int it = 0; it < NITERS; ++it) {
        sinkhorn_half<<<dim3(513, BATCH), 256>>>(0);  // update u (rows of Zh)
        sinkhorn_half<<<dim3(513, BATCH), 256>>>(1);  // update v (rows of ZTh)
    }
    final_kernel<<<dim3((MAUG + 255) / 256, MAUG, BATCH), 256>>>(out);
}